// round 2
// baseline (speedup 1.0000x reference)
#include <cuda_runtime.h>
#include <cuda_bf16.h>
#include <math.h>
#include <stdint.h>

#define BATCH 1024
#define FEAT  2048
#define NCLS  11003
#define NPAD  11008
#define NTILES 172          // NPAD / 64
#define ROWS2 2048          // stacked [v; t]

// ---------------- device scratch (static, no runtime alloc) ----------------
__device__ __nv_bfloat16 g_abuf[ROWS2 * FEAT];       // normalized [v;t] bf16 (8 MB)
__device__ __nv_bfloat16 g_wb[FEAT * NPAD];          // W bf16, padded cols (45 MB)
__device__ float g_colsq[8 * NPAD];
__device__ float g_invn28[NPAD];                     // 28 / ||W_col||
__device__ float g_ll[ROWS2];                        // label logits
__device__ float g_pmax[NTILES * ROWS2];             // blockwise lse partials
__device__ float g_psum[NTILES * ROWS2];
__device__ float g_gal_part[128];
__device__ float g_inst_part[2];
__device__ int   g_lab[BATCH];

// ---------------- prep kernels ----------------
__global__ void normalize_kernel(const float* __restrict__ vis,
                                 const float* __restrict__ txt) {
    int r = blockIdx.x;                 // 0..2047
    const float* src = (r < BATCH) ? (vis + (size_t)r * FEAT)
                                   : (txt + (size_t)(r - BATCH) * FEAT);
    int t = threadIdx.x;                // 256 threads, 8 floats each
    float4 x0 = ((const float4*)src)[t];
    float4 x1 = ((const float4*)src)[t + 256];
    float ss = x0.x*x0.x + x0.y*x0.y + x0.z*x0.z + x0.w*x0.w
             + x1.x*x1.x + x1.y*x1.y + x1.z*x1.z + x1.w*x1.w;
    #pragma unroll
    for (int o = 16; o > 0; o >>= 1) ss += __shfl_xor_sync(0xffffffffu, ss, o);
    __shared__ float ws[8];
    __shared__ float s_rn;
    if ((t & 31) == 0) ws[t >> 5] = ss;
    __syncthreads();
    if (t == 0) {
        float s = 0.f;
        #pragma unroll
        for (int i = 0; i < 8; i++) s += ws[i];
        s_rn = rsqrtf(s);
    }
    __syncthreads();
    float rn = s_rn;
    __nv_bfloat162* dst = (__nv_bfloat162*)(g_abuf + (size_t)r * FEAT);
    dst[2*t]       = __nv_bfloat162(__float2bfloat16(x0.x*rn), __float2bfloat16(x0.y*rn));
    dst[2*t + 1]   = __nv_bfloat162(__float2bfloat16(x0.z*rn), __float2bfloat16(x0.w*rn));
    dst[512 + 2*t]     = __nv_bfloat162(__float2bfloat16(x1.x*rn), __float2bfloat16(x1.y*rn));
    dst[512 + 2*t + 1] = __nv_bfloat162(__float2bfloat16(x1.z*rn), __float2bfloat16(x1.w*rn));
}

// Labels may arrive as int32 (JAX canonicalizes int64 -> int32 without x64)
// or as genuine int64. Detect: for positive int64 little-endian values, every
// odd 32-bit word of the first 64 is zero. For real int32 labels the odds of
// 32 random labels all being 0 is ~0. Only reads lb[2i] AFTER int64 detected,
// so all accesses are in-bounds for the actual buffer size.
__global__ void lab_kernel(const int* __restrict__ lb) {
    int i = threadIdx.x;                // 1 block x 1024 threads
    bool is64 = true;
    #pragma unroll
    for (int j = 1; j < 64; j += 2)
        if (lb[j] != 0) is64 = false;
    g_lab[i] = is64 ? lb[2 * i] : lb[i];
}

__global__ void wprep_kernel(const float* __restrict__ W) {
    int c  = blockIdx.x * 256 + threadIdx.x;   // 0..11007
    int ks = blockIdx.y;                       // 0..7 -> 256 k-rows each
    float ss = 0.f;
    int k0 = ks * 256;
    if (c < NCLS) {
        #pragma unroll 4
        for (int k = k0; k < k0 + 256; k++) {
            float w = W[(size_t)k * NCLS + c];
            ss += w * w;
            g_wb[(size_t)k * NPAD + c] = __float2bfloat16(w);
        }
    } else {
        for (int k = k0; k < k0 + 256; k++)
            g_wb[(size_t)k * NPAD + c] = __float2bfloat16(0.f);
    }
    g_colsq[ks * NPAD + c] = ss;
}

__global__ void invn_kernel() {
    int c = blockIdx.x * 256 + threadIdx.x;
    float s = 0.f;
    #pragma unroll
    for (int i = 0; i < 8; i++) s += g_colsq[i * NPAD + c];
    g_invn28[c] = (c < NCLS) ? 28.0f * rsqrtf(s) : 0.f;
}

// ---------------- mma.sync helpers ----------------
__device__ __forceinline__ void ldmx4(uint32_t* r, uint32_t a) {
    asm volatile("ldmatrix.sync.aligned.m8n8.x4.shared.b16 {%0,%1,%2,%3},[%4];\n"
                 : "=r"(r[0]), "=r"(r[1]), "=r"(r[2]), "=r"(r[3]) : "r"(a));
}
__device__ __forceinline__ void ldmx4t(uint32_t* r, uint32_t a) {
    asm volatile("ldmatrix.sync.aligned.m8n8.x4.trans.shared.b16 {%0,%1,%2,%3},[%4];\n"
                 : "=r"(r[0]), "=r"(r[1]), "=r"(r[2]), "=r"(r[3]) : "r"(a));
}
__device__ __forceinline__ void mma16816(float* c, const uint32_t* a, const uint32_t* b) {
    asm volatile("mma.sync.aligned.m16n8k16.row.col.f32.bf16.bf16.f32 "
                 "{%0,%1,%2,%3},{%4,%5,%6,%7},{%8,%9},{%0,%1,%2,%3};\n"
                 : "+f"(c[0]), "+f"(c[1]), "+f"(c[2]), "+f"(c[3])
                 : "r"(a[0]), "r"(a[1]), "r"(a[2]), "r"(a[3]),
                   "r"(b[0]), "r"(b[1]));
}

#define BM 128
#define BN 64
#define BK 64
#define SA_STRIDE 72   // bf16 elems, 144B rows: ldmatrix conflict-free
#define SB_STRIDE 72

// Block tile 128x64, 4 warps, warp tile 32x64 (each row owned by one warp).
// BKMAJ=true : B staged as [k][n] (gemm1, W), frags via ldmatrix.trans
// BKMAJ=false: B staged as [n][k] (gemm2, tn), frags via ldmatrix
template <bool BKMAJ>
__device__ __forceinline__ void gemm_main(const __nv_bfloat16* __restrict__ Ag,
                                          const __nv_bfloat16* __restrict__ Bg,
                                          int lda, int ldb, int mtile, int ntile,
                                          float c[2][8][4]) {
    __shared__ __nv_bfloat16 sA[BM * SA_STRIDE];
    __shared__ __nv_bfloat16 sB[BN * SB_STRIDE];
    int t = threadIdx.x, warp = t >> 5, lane = t & 31;

    #pragma unroll
    for (int mm = 0; mm < 2; mm++)
        #pragma unroll
        for (int nb = 0; nb < 8; nb++)
            #pragma unroll
            for (int j = 0; j < 4; j++) c[mm][nb][j] = 0.f;

    uint32_t sAb = (uint32_t)__cvta_generic_to_shared(sA);
    uint32_t sBb = (uint32_t)__cvta_generic_to_shared(sB);

    for (int kt = 0; kt < FEAT; kt += BK) {
        // copy A tile 128x64 (1024 uint4)
        const __nv_bfloat16* Asrc = Ag + (size_t)(mtile * BM) * lda + kt;
        #pragma unroll
        for (int i = 0; i < 8; i++) {
            int lin = t + i * 128;
            int row = lin >> 3, q = lin & 7;
            *(uint4*)(sA + row * SA_STRIDE + q * 8) =
                *(const uint4*)(Asrc + (size_t)row * lda + q * 8);
        }
        // copy B tile 64x64 (512 uint4)
        const __nv_bfloat16* Bsrc = BKMAJ
            ? (Bg + (size_t)kt * ldb + ntile * BN)            // rows = k
            : (Bg + (size_t)(ntile * BN) * ldb + kt);         // rows = n
        #pragma unroll
        for (int i = 0; i < 4; i++) {
            int lin = t + i * 128;
            int row = lin >> 3, q = lin & 7;
            *(uint4*)(sB + row * SB_STRIDE + q * 8) =
                *(const uint4*)(Bsrc + (size_t)row * ldb + q * 8);
        }
        __syncthreads();

        #pragma unroll
        for (int ks = 0; ks < 4; ks++) {
            uint32_t a[2][4], b[8][2];
            #pragma unroll
            for (int mm = 0; mm < 2; mm++) {
                uint32_t addr = sAb +
                    ((warp * 32 + mm * 16 + (lane & 15)) * SA_STRIDE +
                     ks * 16 + ((lane >> 4) << 3)) * 2;
                ldmx4(a[mm], addr);
            }
            #pragma unroll
            for (int nb2 = 0; nb2 < 4; nb2++) {
                uint32_t r[4];
                if (BKMAJ) {
                    uint32_t addr = sBb +
                        ((ks * 16 + (lane & 15)) * SB_STRIDE +
                         nb2 * 16 + ((lane >> 4) << 3)) * 2;
                    ldmx4t(r, addr);
                } else {
                    int nrow = nb2 * 16 + (lane & 7) + ((lane >> 4) << 3);
                    int kcol = ks * 16 + (((lane >> 3) & 1) << 3);
                    uint32_t addr = sBb + (nrow * SB_STRIDE + kcol) * 2;
                    ldmx4(r, addr);
                }
                b[nb2 * 2][0] = r[0]; b[nb2 * 2][1] = r[1];
                b[nb2 * 2 + 1][0] = r[2]; b[nb2 * 2 + 1][1] = r[3];
            }
            #pragma unroll
            for (int mm = 0; mm < 2; mm++)
                #pragma unroll
                for (int nb = 0; nb < 8; nb++)
                    mma16816(c[mm][nb], a[mm], b[nb]);
        }
        __syncthreads();
    }
}

// ---------------- GEMM1: logits + fused blockwise logsumexp ----------------
__global__ __launch_bounds__(128, 4) void gemm1_kernel() {
    int ntile = blockIdx.x, mtile = blockIdx.y;
    float c[2][8][4];
    gemm_main<true>(g_abuf, g_wb, FEAT, NPAD, mtile, ntile, c);

    int lane = threadIdx.x & 31, warp = threadIdx.x >> 5;
    int g = lane >> 2, tg = lane & 3;
    #pragma unroll
    for (int mm = 0; mm < 2; mm++)
        #pragma unroll
        for (int pr = 0; pr < 2; pr++) {
            int R = mtile * 128 + warp * 32 + mm * 16 + pr * 8 + g;
            int lbl = g_lab[R & (BATCH - 1)];
            float v[16];
            #pragma unroll
            for (int nb = 0; nb < 8; nb++)
                #pragma unroll
                for (int j = 0; j < 2; j++) {
                    int n = ntile * 64 + nb * 8 + tg * 2 + j;
                    float val = (n < NCLS) ? c[mm][nb][pr * 2 + j] * g_invn28[n]
                                           : -1e30f;
                    if (n == lbl) g_ll[R] = val;
                    v[nb * 2 + j] = val;
                }
            float mx = v[0];
            #pragma unroll
            for (int i = 1; i < 16; i++) mx = fmaxf(mx, v[i]);
            mx = fmaxf(mx, __shfl_xor_sync(0xffffffffu, mx, 1));
            mx = fmaxf(mx, __shfl_xor_sync(0xffffffffu, mx, 2));
            float s = 0.f;
            #pragma unroll
            for (int i = 0; i < 16; i++) s += __expf(v[i] - mx);
            s += __shfl_xor_sync(0xffffffffu, s, 1);
            s += __shfl_xor_sync(0xffffffffu, s, 2);
            if (tg == 0) {
                g_pmax[ntile * ROWS2 + R] = mx;
                g_psum[ntile * ROWS2 + R] = s;
            }
        }
}

// ---------------- GEMM2: sim + fused soft-margin loss ----------------
__global__ __launch_bounds__(128, 4) void gemm2_kernel() {
    int ntile = blockIdx.x, mtile = blockIdx.y;
    float c[2][8][4];
    gemm_main<false>(g_abuf, g_abuf + (size_t)BATCH * FEAT, FEAT, FEAT,
                     mtile, ntile, c);

    int lane = threadIdx.x & 31, warp = threadIdx.x >> 5;
    int g = lane >> 2, tg = lane & 3;
    float local = 0.f;
    #pragma unroll
    for (int mm = 0; mm < 2; mm++)
        #pragma unroll
        for (int pr = 0; pr < 2; pr++) {
            int R = mtile * 128 + warp * 32 + mm * 16 + pr * 8 + g;
            int lr = g_lab[R];
            #pragma unroll
            for (int nb = 0; nb < 8; nb++)
                #pragma unroll
                for (int j = 0; j < 2; j++) {
                    int n = ntile * 64 + nb * 8 + tg * 2 + j;
                    int lc = g_lab[n];
                    float s = c[mm][nb][pr * 2 + j];
                    float x = (lr == lc) ? (-10.f * (s - 0.6f))
                                         : (40.f * (s - 0.4f));
                    local += (x > 15.f) ? x : log1pf(__expf(x));
                }
        }
    #pragma unroll
    for (int o = 16; o > 0; o >>= 1) local += __shfl_xor_sync(0xffffffffu, local, o);
    __shared__ float ws[4];
    if (lane == 0) ws[warp] = local;
    __syncthreads();
    if (threadIdx.x == 0)
        g_gal_part[blockIdx.y * gridDim.x + blockIdx.x] = ws[0] + ws[1] + ws[2] + ws[3];
}

// ---------------- combine: per-row lse + CE partial ----------------
__global__ void combine_kernel() {
    int r = blockIdx.x * 1024 + threadIdx.x;     // 2 blocks x 1024
    float mx = -1e30f;
    for (int i = 0; i < NTILES; i++) mx = fmaxf(mx, g_pmax[i * ROWS2 + r]);
    float s = 0.f;
    for (int i = 0; i < NTILES; i++)
        s += g_psum[i * ROWS2 + r] * __expf(g_pmax[i * ROWS2 + r] - mx);
    float contrib = mx + logf(s) - g_ll[r];

    int lane = threadIdx.x & 31, wid = threadIdx.x >> 5;
    #pragma unroll
    for (int o = 16; o > 0; o >>= 1) contrib += __shfl_xor_sync(0xffffffffu, contrib, o);
    __shared__ float ws[32];
    if (lane == 0) ws[wid] = contrib;
    __syncthreads();
    if (threadIdx.x < 32) {
        float v = ws[threadIdx.x];
        #pragma unroll
        for (int o = 16; o > 0; o >>= 1) v += __shfl_xor_sync(0xffffffffu, v, o);
        if (threadIdx.x == 0) g_inst_part[blockIdx.x] = v;
    }
}

__global__ void finalize_kernel(float* __restrict__ out) {
    float inst = (g_inst_part[0] + g_inst_part[1]) * (1.0f / BATCH);
    float gal = 0.f;
    for (int i = 0; i < 128; i++) gal += g_gal_part[i];
    out[0] = inst;
    out[1] = 2.0f * gal / BATCH;
}

// ---------------- launch ----------------
extern "C" void kernel_launch(void* const* d_in, const int* in_sizes, int n_in,
                              void* d_out, int out_size) {
    const float* vis = (const float*)d_in[0];
    const float* txt = (const float*)d_in[1];
    const int* lab = (const int*)d_in[2];
    const float* W = (const float*)d_in[3];
    float* out = (float*)d_out;

    normalize_kernel<<<ROWS2, 256>>>(vis, txt);
    lab_kernel<<<1, 1024>>>(lab);
    wprep_kernel<<<dim3(43, 8), 256>>>(W);
    invn_kernel<<<43, 256>>>();
    gemm1_kernel<<<dim3(NTILES, 16), 128>>>();
    combine_kernel<<<2, 1024>>>();
    gemm2_kernel<<<dim3(16, 8), 128>>>();
    finalize_kernel<<<1, 1>>>(out);
}

// round 4
// speedup vs baseline: 1.1872x; 1.1872x over previous
#include <cuda_runtime.h>
#include <cuda_bf16.h>
#include <math.h>
#include <stdint.h>

#define BATCH 1024
#define FEAT  2048
#define NCLS  11003
#define NPAD  11008
#define NT1   86            // N tiles of 128 for gemm1
#define NCH   344           // 32-col LSE chunks (NPAD/32)
#define ROWS2 2048          // stacked [v; t]
#define NSTG  32            // FEAT / 64

// ---------------- device scratch (static, no runtime alloc) ----------------
__device__ __align__(128) __nv_bfloat16 g_abuf[ROWS2 * FEAT];   // normalized [v;t]
__device__ __align__(128) __nv_bfloat16 g_wb[FEAT * NPAD];      // W bf16 [k][NPAD]
__device__ float g_colsq[8 * NPAD];
__device__ float g_invn28[NPAD];        // 28 / ||W_col||
__device__ float g_ll[ROWS2];           // label logits
__device__ float g_pmax[NCH * ROWS2];   // chunkwise lse partials
__device__ float g_psum[NCH * ROWS2];
__device__ float g_gal_part[64];
__device__ float g_inst_part[2];
__device__ int   g_lab[BATCH];

// ---------------- prep kernels ----------------
__global__ void normalize_kernel(const float* __restrict__ vis,
                                 const float* __restrict__ txt) {
    int r = blockIdx.x;                 // 0..2047
    const float* src = (r < BATCH) ? (vis + (size_t)r * FEAT)
                                   : (txt + (size_t)(r - BATCH) * FEAT);
    int t = threadIdx.x;                // 256 threads, 8 floats each
    float4 x0 = ((const float4*)src)[t];
    float4 x1 = ((const float4*)src)[t + 256];
    float ss = x0.x*x0.x + x0.y*x0.y + x0.z*x0.z + x0.w*x0.w
             + x1.x*x1.x + x1.y*x1.y + x1.z*x1.z + x1.w*x1.w;
    #pragma unroll
    for (int o = 16; o > 0; o >>= 1) ss += __shfl_xor_sync(0xffffffffu, ss, o);
    __shared__ float ws[8];
    __shared__ float s_rn;
    if ((t & 31) == 0) ws[t >> 5] = ss;
    __syncthreads();
    if (t == 0) {
        float s = 0.f;
        #pragma unroll
        for (int i = 0; i < 8; i++) s += ws[i];
        s_rn = rsqrtf(s);
    }
    __syncthreads();
    float rn = s_rn;
    __nv_bfloat162* dst = (__nv_bfloat162*)(g_abuf + (size_t)r * FEAT);
    dst[2*t]       = __nv_bfloat162(__float2bfloat16(x0.x*rn), __float2bfloat16(x0.y*rn));
    dst[2*t + 1]   = __nv_bfloat162(__float2bfloat16(x0.z*rn), __float2bfloat16(x0.w*rn));
    dst[512 + 2*t]     = __nv_bfloat162(__float2bfloat16(x1.x*rn), __float2bfloat16(x1.y*rn));
    dst[512 + 2*t + 1] = __nv_bfloat162(__float2bfloat16(x1.z*rn), __float2bfloat16(x1.w*rn));
}

// Labels may be int32 (JAX canonicalization) or true int64; detect via the
// high words of the first 64 ints. lb[2i] only touched after int64 confirmed.
__global__ void lab_kernel(const int* __restrict__ lb) {
    int i = threadIdx.x;                // 1 block x 1024 threads
    bool is64 = true;
    #pragma unroll
    for (int j = 1; j < 64; j += 2)
        if (lb[j] != 0) is64 = false;
    g_lab[i] = is64 ? lb[2 * i] : lb[i];
}

__global__ void wprep_kernel(const float* __restrict__ W) {
    int c  = blockIdx.x * 256 + threadIdx.x;   // 0..11007
    int ks = blockIdx.y;                       // 0..7 -> 256 k-rows each
    float ss = 0.f;
    int k0 = ks * 256;
    if (c < NCLS) {
        #pragma unroll 4
        for (int k = k0; k < k0 + 256; k++) {
            float w = W[(size_t)k * NCLS + c];
            ss += w * w;
            g_wb[(size_t)k * NPAD + c] = __float2bfloat16(w);
        }
    } else {
        for (int k = k0; k < k0 + 256; k++)
            g_wb[(size_t)k * NPAD + c] = __float2bfloat16(0.f);
    }
    g_colsq[ks * NPAD + c] = ss;
}

__global__ void invn_kernel() {
    int c = blockIdx.x * 256 + threadIdx.x;
    float s = 0.f;
    #pragma unroll
    for (int i = 0; i < 8; i++) s += g_colsq[i * NPAD + c];
    g_invn28[c] = (c < NCLS) ? 28.0f * rsqrtf(s) : 0.f;
}

// ---------------- mma helpers ----------------
__device__ __forceinline__ void ldmx4(uint32_t* r, uint32_t a) {
    asm volatile("ldmatrix.sync.aligned.m8n8.x4.shared.b16 {%0,%1,%2,%3},[%4];\n"
                 : "=r"(r[0]), "=r"(r[1]), "=r"(r[2]), "=r"(r[3]) : "r"(a));
}
__device__ __forceinline__ void ldmx4t(uint32_t* r, uint32_t a) {
    asm volatile("ldmatrix.sync.aligned.m8n8.x4.trans.shared.b16 {%0,%1,%2,%3},[%4];\n"
                 : "=r"(r[0]), "=r"(r[1]), "=r"(r[2]), "=r"(r[3]) : "r"(a));
}
__device__ __forceinline__ void mma16816(float* c, const uint32_t* a, const uint32_t* b) {
    asm volatile("mma.sync.aligned.m16n8k16.row.col.f32.bf16.bf16.f32 "
                 "{%0,%1,%2,%3},{%4,%5,%6,%7},{%8,%9},{%0,%1,%2,%3};\n"
                 : "+f"(c[0]), "+f"(c[1]), "+f"(c[2]), "+f"(c[3])
                 : "r"(a[0]), "r"(a[1]), "r"(a[2]), "r"(a[3]),
                   "r"(b[0]), "r"(b[1]));
}
__device__ __forceinline__ void cpa16(uint32_t dst, const void* src) {
    asm volatile("cp.async.cg.shared.global [%0], [%1], 16;" :: "r"(dst), "l"(src));
}
__device__ __forceinline__ void cpa_commit() {
    asm volatile("cp.async.commit_group;" ::: "memory");
}
template <int N> __device__ __forceinline__ void cpa_wait() {
    asm volatile("cp.async.wait_group %0;" :: "n"(N) : "memory");
}

// ======================= pipelined 128x128x64 GEMM core =======================
// 256 threads, 8 warps: warp_m = warp&1 (64 rows), warp_n = warp>>1 (32 cols).
// 3-stage cp.async pipeline. A always [m][k] K-major.
// BKMAJ=true : B staged [k=64][n=128] (gemm1, g_wb), frags via ldmatrix.trans
// BKMAJ=false: B staged [n=128][k=64] (gemm2, t rows), frags via ldmatrix
#define A_ST 72               // elems; 144B rows
#define A_BYTES (128 * A_ST * 2)

template <bool BKMAJ>
__device__ __forceinline__ void gemm_pipe(const __nv_bfloat16* __restrict__ Ag,
                                          const __nv_bfloat16* __restrict__ Bg,
                                          int ldb, int mtile, int ntile,
                                          char* smem, float c[4][4][4]) {
    constexpr int B_ST = BKMAJ ? 136 : 72;        // 272B / 144B rows
    constexpr int B_BYTES = (BKMAJ ? 64 : 128) * B_ST * 2;
    constexpr int STG = A_BYTES + B_BYTES;

    int tid = threadIdx.x, warp = tid >> 5, lane = tid & 31;
    int wm = warp & 1, wn = warp >> 1;
    uint32_t sb = (uint32_t)__cvta_generic_to_shared(smem);

    #pragma unroll
    for (int mf = 0; mf < 4; mf++)
        #pragma unroll
        for (int nf = 0; nf < 4; nf++)
            #pragma unroll
            for (int j = 0; j < 4; j++) c[mf][nf][j] = 0.f;

    const __nv_bfloat16* Abase = Ag + (size_t)(mtile * 128) * FEAT;

    auto issue_stage = [&](int kt, int buf) {
        uint32_t ab = sb + buf * STG;
        uint32_t bb = ab + A_BYTES;
        #pragma unroll
        for (int i = 0; i < 4; i++) {            // A: 128x64 = 1024 16B chunks
            int ch = tid + i * 256;
            int row = ch >> 3, q = ch & 7;
            cpa16(ab + row * 144 + q * 16,
                  Abase + (size_t)row * FEAT + kt * 64 + q * 8);
        }
        if (BKMAJ) {
            #pragma unroll
            for (int i = 0; i < 4; i++) {        // B: 64 k-rows x 128 n
                int ch = tid + i * 256;
                int row = ch >> 4, q = ch & 15;
                cpa16(bb + row * 272 + q * 16,
                      Bg + (size_t)(kt * 64 + row) * ldb + ntile * 128 + q * 8);
            }
        } else {
            #pragma unroll
            for (int i = 0; i < 4; i++) {        // B: 128 n-rows x 64 k
                int ch = tid + i * 256;
                int row = ch >> 3, q = ch & 7;
                cpa16(bb + row * 144 + q * 16,
                      Bg + (size_t)(ntile * 128 + row) * ldb + kt * 64 + q * 8);
            }
        }
        cpa_commit();
    };

    issue_stage(0, 0);
    issue_stage(1, 1);

    for (int kt = 0; kt < NSTG; kt++) {
        int buf = kt % 3;
        if (kt < NSTG - 1) cpa_wait<1>(); else cpa_wait<0>();
        __syncthreads();
        if (kt + 2 < NSTG) issue_stage(kt + 2, (kt + 2) % 3);

        uint32_t ab = sb + buf * STG;
        uint32_t bb = ab + A_BYTES;
        #pragma unroll
        for (int ks = 0; ks < 4; ks++) {
            uint32_t a[4][4], b[4][2];
            #pragma unroll
            for (int mf = 0; mf < 4; mf++)
                ldmx4(a[mf], ab + ((wm * 64 + mf * 16 + (lane & 15)) * A_ST +
                                   ks * 16 + ((lane >> 4) << 3)) * 2);
            #pragma unroll
            for (int nh = 0; nh < 2; nh++) {
                uint32_t r[4];
                if (BKMAJ) {
                    ldmx4t(r, bb + ((ks * 16 + (lane & 15)) * B_ST +
                                    wn * 32 + nh * 16 + ((lane >> 4) << 3)) * 2);
                } else {
                    int nrow = wn * 32 + nh * 16 + (lane & 7) + ((lane >> 4) << 3);
                    int kcol = ks * 16 + (((lane >> 3) & 1) << 3);
                    ldmx4(r, bb + (nrow * B_ST + kcol) * 2);
                }
                b[nh * 2][0] = r[0]; b[nh * 2][1] = r[1];
                b[nh * 2 + 1][0] = r[2]; b[nh * 2 + 1][1] = r[3];
            }
            #pragma unroll
            for (int mf = 0; mf < 4; mf++)
                #pragma unroll
                for (int nf = 0; nf < 4; nf++)
                    mma16816(c[mf][nf], a[mf], b[nf]);
        }
        __syncthreads();
    }
}

#define G1_SMEM (3 * (A_BYTES + 64 * 136 * 2))    // 107520
#define G2_SMEM (3 * (A_BYTES + 128 * 72 * 2))    // 110592

// ---------------- GEMM1: logits + fused chunkwise logsumexp ----------------
__global__ __launch_bounds__(256, 2) void gemm1_kernel() {
    extern __shared__ char smem[];
    __shared__ float sInv[128];
    int ntile = blockIdx.x, mtile = blockIdx.y;
    int tid = threadIdx.x;
    if (tid < 128) sInv[tid] = g_invn28[ntile * 128 + tid];

    float c[4][4][4];
    gemm_pipe<true>(g_abuf, g_wb, NPAD, mtile, ntile, smem, c);

    int lane = tid & 31, warp = tid >> 5;
    int wm = warp & 1, wn = warp >> 1;
    int g = lane >> 2, tg = lane & 3;
    #pragma unroll
    for (int mf = 0; mf < 4; mf++)
        #pragma unroll
        for (int pr = 0; pr < 2; pr++) {
            int R = mtile * 128 + wm * 64 + mf * 16 + pr * 8 + g;
            int lbl = g_lab[R & (BATCH - 1)];
            float v[8];
            float mx = -1e30f;
            #pragma unroll
            for (int nf = 0; nf < 4; nf++)
                #pragma unroll
                for (int j = 0; j < 2; j++) {
                    int nl = wn * 32 + nf * 8 + tg * 2 + j;
                    int n = ntile * 128 + nl;
                    float val = c[mf][nf][pr * 2 + j] * sInv[nl];
                    if (n >= NCLS) val = -1e30f;
                    if (n == lbl) g_ll[R] = val;
                    v[nf * 2 + j] = val;
                    mx = fmaxf(mx, val);
                }
            mx = fmaxf(mx, __shfl_xor_sync(0xffffffffu, mx, 1));
            mx = fmaxf(mx, __shfl_xor_sync(0xffffffffu, mx, 2));
            float s = 0.f;
            #pragma unroll
            for (int i = 0; i < 8; i++) s += __expf(v[i] - mx);
            s += __shfl_xor_sync(0xffffffffu, s, 1);
            s += __shfl_xor_sync(0xffffffffu, s, 2);
            if (tg == 0) {
                int chunk = ntile * 4 + wn;
                g_pmax[chunk * ROWS2 + R] = mx;
                g_psum[chunk * ROWS2 + R] = s;
            }
        }
}

// ---------------- GEMM2: sim + fused soft-margin loss ----------------
__global__ __launch_bounds__(256, 2) void gemm2_kernel() {
    extern __shared__ char smem[];
    int ntile = blockIdx.x, mtile = blockIdx.y;

    float c[4][4][4];
    gemm_pipe<false>(g_abuf, g_abuf + (size_t)BATCH * FEAT, FEAT,
                     mtile, ntile, smem, c);

    int tid = threadIdx.x, lane = tid & 31, warp = tid >> 5;
    int wm = warp & 1, wn = warp >> 1;
    int g = lane >> 2, tg = lane & 3;
    float local = 0.f;
    #pragma unroll
    for (int mf = 0; mf < 4; mf++)
        #pragma unroll
        for (int pr = 0; pr < 2; pr++) {
            int R = mtile * 128 + wm * 64 + mf * 16 + pr * 8 + g;
            int lr = g_lab[R];
            #pragma unroll
            for (int nf = 0; nf < 4; nf++)
                #pragma unroll
                for (int j = 0; j < 2; j++) {
                    int n = ntile * 128 + wn * 32 + nf * 8 + tg * 2 + j;
                    int lc = g_lab[n];
                    float s = c[mf][nf][pr * 2 + j];
                    float x = (lr == lc) ? (-10.f * (s - 0.6f))
                                         : (40.f * (s - 0.4f));
                    local += (x > 15.f) ? x : log1pf(__expf(x));
                }
        }
    #pragma unroll
    for (int o = 16; o > 0; o >>= 1) local += __shfl_xor_sync(0xffffffffu, local, o);
    __shared__ float ws[8];
    if (lane == 0) ws[warp] = local;
    __syncthreads();
    if (tid == 0) {
        float t = 0.f;
        #pragma unroll
        for (int i = 0; i < 8; i++) t += ws[i];
        g_gal_part[blockIdx.y * gridDim.x + blockIdx.x] = t;
    }
}

// ---------------- combine: per-row lse + CE partial ----------------
__global__ void combine_kernel() {
    int r = blockIdx.x * 1024 + threadIdx.x;     // 2 blocks x 1024
    float mx = -1e30f;
    for (int i = 0; i < NCH; i++) mx = fmaxf(mx, g_pmax[i * ROWS2 + r]);
    float s = 0.f;
    for (int i = 0; i < NCH; i++)
        s += g_psum[i * ROWS2 + r] * __expf(g_pmax[i * ROWS2 + r] - mx);
    float contrib = mx + logf(s) - g_ll[r];

    int lane = threadIdx.x & 31, wid = threadIdx.x >> 5;
    #pragma unroll
    for (int o = 16; o > 0; o >>= 1) contrib += __shfl_xor_sync(0xffffffffu, contrib, o);
    __shared__ float ws[32];
    if (lane == 0) ws[wid] = contrib;
    __syncthreads();
    if (threadIdx.x < 32) {
        float v = ws[threadIdx.x];
        #pragma unroll
        for (int o = 16; o > 0; o >>= 1) v += __shfl_xor_sync(0xffffffffu, v, o);
        if (threadIdx.x == 0) g_inst_part[blockIdx.x] = v;
    }
}

__global__ void finalize_kernel(float* __restrict__ out) {
    float inst = (g_inst_part[0] + g_inst_part[1]) * (1.0f / BATCH);
    float gal = 0.f;
    for (int i = 0; i < 64; i++) gal += g_gal_part[i];
    out[0] = inst;
    out[1] = 2.0f * gal / BATCH;
}

// ---------------- launch ----------------
extern "C" void kernel_launch(void* const* d_in, const int* in_sizes, int n_in,
                              void* d_out, int out_size) {
    const float* vis = (const float*)d_in[0];
    const float* txt = (const float*)d_in[1];
    const int* lab = (const int*)d_in[2];
    const float* W = (const float*)d_in[3];
    float* out = (float*)d_out;

    cudaFuncSetAttribute(gemm1_kernel,
                         cudaFuncAttributeMaxDynamicSharedMemorySize, G1_SMEM);
    cudaFuncSetAttribute(gemm2_kernel,
                         cudaFuncAttributeMaxDynamicSharedMemorySize, G2_SMEM);

    normalize_kernel<<<ROWS2, 256>>>(vis, txt);
    lab_kernel<<<1, 1024>>>(lab);
    wprep_kernel<<<dim3(43, 8), 256>>>(W);
    invn_kernel<<<43, 256>>>();
    gemm1_kernel<<<dim3(NT1, 16), 256, G1_SMEM>>>();
    combine_kernel<<<2, 1024>>>();
    gemm2_kernel<<<dim3(8, 8), 256, G2_SMEM>>>();
    finalize_kernel<<<1, 1>>>(out);
}

// round 5
// speedup vs baseline: 1.2204x; 1.0280x over previous
#include <cuda_runtime.h>
#include <cuda_bf16.h>
#include <cuda_fp8.h>
#include <math.h>
#include <stdint.h>

#define BATCH 1024
#define FEAT  2048
#define NCLS  11003
#define NPAD  11008
#define NT1   86            // N tiles of 128 for gemm1
#define NCH   344           // 32-col LSE chunks (NPAD/32)
#define ROWS2 2048          // stacked [v; t]

#define ASCALE 64.0f
#define WSCALE 4.0f

// ---------------- device scratch (static, no runtime alloc) ----------------
__device__ __align__(128) __nv_bfloat16 g_abuf[ROWS2 * FEAT];   // normalized [v;t] bf16 (gemm2)
__device__ __align__(128) uint8_t g_a8[(size_t)ROWS2 * FEAT];   // fp8 v-hat * 64
__device__ __align__(128) uint8_t g_w8t[(size_t)NPAD * FEAT];   // fp8 W^T [n][k] * 4
__device__ float g_colsqp[16 * NPAD];   // per-128k col sq partials (fp32 W)
__device__ float g_invn[NPAD];          // 28 / (256 * ||W_col||)
__device__ float g_ll[ROWS2];           // label logits
__device__ float g_pmax[NCH * ROWS2];   // chunkwise lse partials
__device__ float g_psum[NCH * ROWS2];
__device__ float g_gal_part[64];
__device__ float g_inst_part[2];
__device__ int   g_lab[BATCH];

__device__ __forceinline__ uint8_t to_e4m3(float x) {
    __nv_fp8_e4m3 v(x);
    return *reinterpret_cast<uint8_t*>(&v);
}

// ---------------- prep: normalize rows + labels ----------------
__global__ void normalize_kernel(const float* __restrict__ vis,
                                 const float* __restrict__ txt,
                                 const int* __restrict__ lb) {
    int r = blockIdx.x;                 // 0..2047
    int t = threadIdx.x;                // 256 threads, 8 floats each

    if (r == 0) {
        // labels may be int32 (JAX canonicalization) or true int64; detect via
        // high words of the first 64 ints. lb[2i] read only after int64 confirmed.
        bool is64 = true;
        #pragma unroll
        for (int j = 1; j < 64; j += 2)
            if (lb[j] != 0) is64 = false;
        #pragma unroll
        for (int i = 0; i < 4; i++) {
            int idx = t + 256 * i;
            g_lab[idx] = is64 ? lb[2 * idx] : lb[idx];
        }
    }

    const float* src = (r < BATCH) ? (vis + (size_t)r * FEAT)
                                   : (txt + (size_t)(r - BATCH) * FEAT);
    float4 x0 = ((const float4*)src)[t];
    float4 x1 = ((const float4*)src)[t + 256];
    float ss = x0.x*x0.x + x0.y*x0.y + x0.z*x0.z + x0.w*x0.w
             + x1.x*x1.x + x1.y*x1.y + x1.z*x1.z + x1.w*x1.w;
    #pragma unroll
    for (int o = 16; o > 0; o >>= 1) ss += __shfl_xor_sync(0xffffffffu, ss, o);
    __shared__ float ws[8];
    __shared__ float s_rn;
    if ((t & 31) == 0) ws[t >> 5] = ss;
    __syncthreads();
    if (t == 0) {
        float s = 0.f;
        #pragma unroll
        for (int i = 0; i < 8; i++) s += ws[i];
        s_rn = rsqrtf(s);
    }
    __syncthreads();
    float rn = s_rn;
    __nv_bfloat162* dst = (__nv_bfloat162*)(g_abuf + (size_t)r * FEAT);
    dst[2*t]       = __nv_bfloat162(__float2bfloat16(x0.x*rn), __float2bfloat16(x0.y*rn));
    dst[2*t + 1]   = __nv_bfloat162(__float2bfloat16(x0.z*rn), __float2bfloat16(x0.w*rn));
    dst[512 + 2*t]     = __nv_bfloat162(__float2bfloat16(x1.x*rn), __float2bfloat16(x1.y*rn));
    dst[512 + 2*t + 1] = __nv_bfloat162(__float2bfloat16(x1.z*rn), __float2bfloat16(x1.w*rn));

    float fa = rn * ASCALE;
    uchar4 p0 = make_uchar4(to_e4m3(x0.x*fa), to_e4m3(x0.y*fa),
                            to_e4m3(x0.z*fa), to_e4m3(x0.w*fa));
    uchar4 p1 = make_uchar4(to_e4m3(x1.x*fa), to_e4m3(x1.y*fa),
                            to_e4m3(x1.z*fa), to_e4m3(x1.w*fa));
    uint32_t* d8 = (uint32_t*)(g_a8 + (size_t)r * FEAT);
    d8[t]       = *reinterpret_cast<uint32_t*>(&p0);
    d8[t + 256] = *reinterpret_cast<uint32_t*>(&p1);
}

// ---------------- prep: transpose W -> fp8 [n][k] + colsq partials ----------------
// block (32,8): c-tile 32 cols, k-tile 128 rows
__global__ void wtrans_kernel(const float* __restrict__ W) {
    __shared__ float s[128][33];
    __shared__ float sq[8][33];
    int c0 = blockIdx.x * 32, k0 = blockIdx.y * 128;
    int tx = threadIdx.x, ty = threadIdx.y;
    int c = c0 + tx;
    float p = 0.f;
    #pragma unroll
    for (int i = 0; i < 16; i++) {
        int k = k0 + ty + 8 * i;
        float w = (c < NCLS) ? W[(size_t)k * NCLS + c] : 0.f;
        s[ty + 8 * i][tx] = w;
        p += w * w;
    }
    sq[ty][tx] = p;
    __syncthreads();
    if (ty == 0) {
        float ssum = 0.f;
        #pragma unroll
        for (int i = 0; i < 8; i++) ssum += sq[i][tx];
        g_colsqp[blockIdx.y * NPAD + c] = ssum;
    }
    // store fp8 transposed: 32 n-rows x 128 k-bytes
    #pragma unroll
    for (int j = 0; j < 4; j++) {
        int nl = ty + 8 * j;           // 0..31
        int kq = tx;                   // 0..31 -> 4 bytes each
        uchar4 pk = make_uchar4(to_e4m3(s[4*kq+0][nl] * WSCALE),
                                to_e4m3(s[4*kq+1][nl] * WSCALE),
                                to_e4m3(s[4*kq+2][nl] * WSCALE),
                                to_e4m3(s[4*kq+3][nl] * WSCALE));
        *(uint32_t*)(g_w8t + (size_t)(c0 + nl) * FEAT + k0 + 4 * kq) =
            *reinterpret_cast<uint32_t*>(&pk);
    }
}

__global__ void invn_kernel() {
    int c = blockIdx.x * 256 + threadIdx.x;
    float s = 0.f;
    #pragma unroll
    for (int i = 0; i < 16; i++) s += g_colsqp[i * NPAD + c];
    g_invn[c] = (c < NCLS) ? (28.0f / (ASCALE * WSCALE)) * rsqrtf(s) : 0.f;
}

// ---------------- mma helpers ----------------
__device__ __forceinline__ void ldmx4(uint32_t* r, uint32_t a) {
    asm volatile("ldmatrix.sync.aligned.m8n8.x4.shared.b16 {%0,%1,%2,%3},[%4];\n"
                 : "=r"(r[0]), "=r"(r[1]), "=r"(r[2]), "=r"(r[3]) : "r"(a));
}
__device__ __forceinline__ void mma16816(float* c, const uint32_t* a, const uint32_t* b) {
    asm volatile("mma.sync.aligned.m16n8k16.row.col.f32.bf16.bf16.f32 "
                 "{%0,%1,%2,%3},{%4,%5,%6,%7},{%8,%9},{%0,%1,%2,%3};\n"
                 : "+f"(c[0]), "+f"(c[1]), "+f"(c[2]), "+f"(c[3])
                 : "r"(a[0]), "r"(a[1]), "r"(a[2]), "r"(a[3]),
                   "r"(b[0]), "r"(b[1]));
}
__device__ __forceinline__ void mma16832f8(float* c, const uint32_t* a, const uint32_t* b) {
    asm volatile("mma.sync.aligned.m16n8k32.row.col.f32.e4m3.e4m3.f32 "
                 "{%0,%1,%2,%3},{%4,%5,%6,%7},{%8,%9},{%0,%1,%2,%3};\n"
                 : "+f"(c[0]), "+f"(c[1]), "+f"(c[2]), "+f"(c[3])
                 : "r"(a[0]), "r"(a[1]), "r"(a[2]), "r"(a[3]),
                   "r"(b[0]), "r"(b[1]));
}
__device__ __forceinline__ void cpa16(uint32_t dst, const void* src) {
    asm volatile("cp.async.cg.shared.global [%0], [%1], 16;" :: "r"(dst), "l"(src));
}
__device__ __forceinline__ void cpa_commit() {
    asm volatile("cp.async.commit_group;" ::: "memory");
}
template <int N> __device__ __forceinline__ void cpa_wait() {
    asm volatile("cp.async.wait_group %0;" :: "n"(N) : "memory");
}

// ======================= GEMM1: fp8 128x128x128B pipeline =======================
// 256 threads, 8 warps: wm = warp&1 (64 rows), wn = warp>>1 (32 cols).
// Stage: A 128 rows x 128 k-bytes (stride 144) + B 128 n-rows x 128 k-bytes.
#define F8_ST   144
#define F8_TB   (128 * F8_ST)           // 18432 per tile
#define F8_STG  (2 * F8_TB)             // 36864
#define G1_SMEM (3 * F8_STG)            // 110592
#define G1_NSTG 16                      // FEAT / 128

__global__ __launch_bounds__(256, 2) void gemm1_kernel() {
    extern __shared__ char smem[];
    __shared__ float sInv[128];
    int ntile = blockIdx.x, mtile = blockIdx.y;
    int tid = threadIdx.x, warp = tid >> 5, lane = tid & 31;
    int wm = warp & 1, wn = warp >> 1;
    if (tid < 128) sInv[tid] = g_invn[ntile * 128 + tid];

    uint32_t sb = (uint32_t)__cvta_generic_to_shared(smem);
    float c[4][4][4];
    #pragma unroll
    for (int mf = 0; mf < 4; mf++)
        #pragma unroll
        for (int nf = 0; nf < 4; nf++)
            #pragma unroll
            for (int j = 0; j < 4; j++) c[mf][nf][j] = 0.f;

    const uint8_t* Abase = g_a8 + (size_t)(mtile * 128) * FEAT;
    const uint8_t* Bbase = g_w8t + (size_t)(ntile * 128) * FEAT;

    auto issue_stage = [&](int kt, int buf) {
        uint32_t ab = sb + buf * F8_STG;
        uint32_t bb = ab + F8_TB;
        #pragma unroll
        for (int i = 0; i < 4; i++) {            // A: 128 x 128B = 1024 chunks
            int ch = tid + i * 256;
            int row = ch >> 3, q = ch & 7;
            cpa16(ab + row * F8_ST + q * 16,
                  Abase + (size_t)row * FEAT + kt * 128 + q * 16);
        }
        #pragma unroll
        for (int i = 0; i < 4; i++) {            // B: 128 x 128B
            int ch = tid + i * 256;
            int row = ch >> 3, q = ch & 7;
            cpa16(bb + row * F8_ST + q * 16,
                  Bbase + (size_t)row * FEAT + kt * 128 + q * 16);
        }
        cpa_commit();
    };

    issue_stage(0, 0);
    issue_stage(1, 1);

    for (int kt = 0; kt < G1_NSTG; kt++) {
        int buf = kt % 3;
        if (kt < G1_NSTG - 1) cpa_wait<1>(); else cpa_wait<0>();
        __syncthreads();
        if (kt + 2 < G1_NSTG) issue_stage(kt + 2, (kt + 2) % 3);

        uint32_t ab = sb + buf * F8_STG;
        uint32_t bb = ab + F8_TB;
        #pragma unroll
        for (int ks = 0; ks < 4; ks++) {         // 4 x k32
            uint32_t a[4][4], b[4][2];
            #pragma unroll
            for (int mf = 0; mf < 4; mf++)
                ldmx4(a[mf], ab + (wm * 64 + mf * 16 + (lane & 15)) * F8_ST +
                              ks * 32 + ((lane >> 4) << 4));
            #pragma unroll
            for (int nh = 0; nh < 2; nh++) {
                uint32_t r[4];
                int nrow = wn * 32 + nh * 16 + (lane & 7) + ((lane >> 4) << 3);
                int kcol = ks * 32 + (((lane >> 3) & 1) << 4);
                ldmx4(r, bb + nrow * F8_ST + kcol);
                b[nh * 2][0] = r[0]; b[nh * 2][1] = r[1];
                b[nh * 2 + 1][0] = r[2]; b[nh * 2 + 1][1] = r[3];
            }
            #pragma unroll
            for (int mf = 0; mf < 4; mf++)
                #pragma unroll
                for (int nf = 0; nf < 4; nf++)
                    mma16832f8(c[mf][nf], a[mf], b[nf]);
        }
        __syncthreads();
    }

    // -------- epilogue: chunkwise logsumexp --------
    int g = lane >> 2, tg = lane & 3;
    #pragma unroll
    for (int mf = 0; mf < 4; mf++)
        #pragma unroll
        for (int pr = 0; pr < 2; pr++) {
            int R = mtile * 128 + wm * 64 + mf * 16 + pr * 8 + g;
            int lbl = g_lab[R & (BATCH - 1)];
            float v[8];
            float mx = -1e30f;
            #pragma unroll
            for (int nf = 0; nf < 4; nf++)
                #pragma unroll
                for (int j = 0; j < 2; j++) {
                    int nl = wn * 32 + nf * 8 + tg * 2 + j;
                    int n = ntile * 128 + nl;
                    float val = c[mf][nf][pr * 2 + j] * sInv[nl];
                    if (n >= NCLS) val = -1e30f;
                    if (n == lbl) g_ll[R] = val;
                    v[nf * 2 + j] = val;
                    mx = fmaxf(mx, val);
                }
            mx = fmaxf(mx, __shfl_xor_sync(0xffffffffu, mx, 1));
            mx = fmaxf(mx, __shfl_xor_sync(0xffffffffu, mx, 2));
            float s = 0.f;
            #pragma unroll
            for (int i = 0; i < 8; i++) s += __expf(v[i] - mx);
            s += __shfl_xor_sync(0xffffffffu, s, 1);
            s += __shfl_xor_sync(0xffffffffu, s, 2);
            if (tg == 0) {
                int chunk = ntile * 4 + wn;
                g_pmax[chunk * ROWS2 + R] = mx;
                g_psum[chunk * ROWS2 + R] = s;
            }
        }
}

// ======================= GEMM2: bf16 128x128x64 pipeline =======================
#define A_ST 72
#define A_BYTES (128 * A_ST * 2)
#define G2_STG  (A_BYTES + 128 * A_ST * 2)
#define G2_SMEM (3 * G2_STG)            // 110592
#define NSTG2 32

__global__ __launch_bounds__(256, 2) void gemm2_kernel() {
    extern __shared__ char smem[];
    int ntile = blockIdx.x, mtile = blockIdx.y;
    int tid = threadIdx.x, warp = tid >> 5, lane = tid & 31;
    int wm = warp & 1, wn = warp >> 1;
    uint32_t sb = (uint32_t)__cvta_generic_to_shared(smem);

    float c[4][4][4];
    #pragma unroll
    for (int mf = 0; mf < 4; mf++)
        #pragma unroll
        for (int nf = 0; nf < 4; nf++)
            #pragma unroll
            for (int j = 0; j < 4; j++) c[mf][nf][j] = 0.f;

    const __nv_bfloat16* Abase = g_abuf + (size_t)(mtile * 128) * FEAT;
    const __nv_bfloat16* Bbase = g_abuf + (size_t)(BATCH + ntile * 128) * FEAT;

    auto issue_stage = [&](int kt, int buf) {
        uint32_t ab = sb + buf * G2_STG;
        uint32_t bb = ab + A_BYTES;
        #pragma unroll
        for (int i = 0; i < 4; i++) {
            int ch = tid + i * 256;
            int row = ch >> 3, q = ch & 7;
            cpa16(ab + row * 144 + q * 16,
                  Abase + (size_t)row * FEAT + kt * 64 + q * 8);
        }
        #pragma unroll
        for (int i = 0; i < 4; i++) {
            int ch = tid + i * 256;
            int row = ch >> 3, q = ch & 7;
            cpa16(bb + row * 144 + q * 16,
                  Bbase + (size_t)row * FEAT + kt * 64 + q * 8);
        }
        cpa_commit();
    };

    issue_stage(0, 0);
    issue_stage(1, 1);

    for (int kt = 0; kt < NSTG2; kt++) {
        int buf = kt % 3;
        if (kt < NSTG2 - 1) cpa_wait<1>(); else cpa_wait<0>();
        __syncthreads();
        if (kt + 2 < NSTG2) issue_stage(kt + 2, (kt + 2) % 3);

        uint32_t ab = sb + buf * G2_STG;
        uint32_t bb = ab + A_BYTES;
        #pragma unroll
        for (int ks = 0; ks < 4; ks++) {
            uint32_t a[4][4], b[4][2];
            #pragma unroll
            for (int mf = 0; mf < 4; mf++)
                ldmx4(a[mf], ab + ((wm * 64 + mf * 16 + (lane & 15)) * A_ST +
                                   ks * 16 + ((lane >> 4) << 3)) * 2);
            #pragma unroll
            for (int nh = 0; nh < 2; nh++) {
                uint32_t r[4];
                int nrow = wn * 32 + nh * 16 + (lane & 7) + ((lane >> 4) << 3);
                int kcol = ks * 16 + (((lane >> 3) & 1) << 3);
                ldmx4(r, bb + (nrow * A_ST + kcol) * 2);
                b[nh * 2][0] = r[0]; b[nh * 2][1] = r[1];
                b[nh * 2 + 1][0] = r[2]; b[nh * 2 + 1][1] = r[3];
            }
            #pragma unroll
            for (int mf = 0; mf < 4; mf++)
                #pragma unroll
                for (int nf = 0; nf < 4; nf++)
                    mma16816(c[mf][nf], a[mf], b[nf]);
        }
        __syncthreads();
    }

    int g = lane >> 2, tg = lane & 3;
    float local = 0.f;
    #pragma unroll
    for (int mf = 0; mf < 4; mf++)
        #pragma unroll
        for (int pr = 0; pr < 2; pr++) {
            int R = mtile * 128 + wm * 64 + mf * 16 + pr * 8 + g;
            int lr = g_lab[R];
            #pragma unroll
            for (int nf = 0; nf < 4; nf++)
                #pragma unroll
                for (int j = 0; j < 2; j++) {
                    int n = ntile * 128 + wn * 32 + nf * 8 + tg * 2 + j;
                    int lc = g_lab[n];
                    float s = c[mf][nf][pr * 2 + j];
                    float x = (lr == lc) ? (-10.f * (s - 0.6f))
                                         : (40.f * (s - 0.4f));
                    local += (x > 15.f) ? x : log1pf(__expf(x));
                }
        }
    #pragma unroll
    for (int o = 16; o > 0; o >>= 1) local += __shfl_xor_sync(0xffffffffu, local, o);
    __shared__ float ws[8];
    if (lane == 0) ws[warp] = local;
    __syncthreads();
    if (tid == 0) {
        float t = 0.f;
        #pragma unroll
        for (int i = 0; i < 8; i++) t += ws[i];
        g_gal_part[blockIdx.y * gridDim.x + blockIdx.x] = t;
    }
}

// ---------------- combine: per-row lse + CE partial ----------------
__global__ void combine_kernel() {
    int r = blockIdx.x * 1024 + threadIdx.x;     // 2 blocks x 1024
    float mx = -1e30f;
    for (int i = 0; i < NCH; i++) mx = fmaxf(mx, g_pmax[i * ROWS2 + r]);
    float s = 0.f;
    for (int i = 0; i < NCH; i++)
        s += g_psum[i * ROWS2 + r] * __expf(g_pmax[i * ROWS2 + r] - mx);
    float contrib = mx + logf(s) - g_ll[r];

    int lane = threadIdx.x & 31, wid = threadIdx.x >> 5;
    #pragma unroll
    for (int o = 16; o > 0; o >>= 1) contrib += __shfl_xor_sync(0xffffffffu, contrib, o);
    __shared__ float ws[32];
    if (lane == 0) ws[wid] = contrib;
    __syncthreads();
    if (threadIdx.x < 32) {
        float v = ws[threadIdx.x];
        #pragma unroll
        for (int o = 16; o > 0; o >>= 1) v += __shfl_xor_sync(0xffffffffu, v, o);
        if (threadIdx.x == 0) g_inst_part[blockIdx.x] = v;
    }
}

__global__ void finalize_kernel(float* __restrict__ out) {
    float inst = (g_inst_part[0] + g_inst_part[1]) * (1.0f / BATCH);
    float gal = 0.f;
    for (int i = 0; i < 64; i++) gal += g_gal_part[i];
    out[0] = inst;
    out[1] = 2.0f * gal / BATCH;
}

// ---------------- launch ----------------
extern "C" void kernel_launch(void* const* d_in, const int* in_sizes, int n_in,
                              void* d_out, int out_size) {
    const float* vis = (const float*)d_in[0];
    const float* txt = (const float*)d_in[1];
    const int* lab = (const int*)d_in[2];
    const float* W = (const float*)d_in[3];
    float* out = (float*)d_out;

    cudaFuncSetAttribute(gemm1_kernel,
                         cudaFuncAttributeMaxDynamicSharedMemorySize, G1_SMEM);
    cudaFuncSetAttribute(gemm2_kernel,
                         cudaFuncAttributeMaxDynamicSharedMemorySize, G2_SMEM);

    normalize_kernel<<<ROWS2, 256>>>(vis, txt, lab);
    wtrans_kernel<<<dim3(NPAD / 32, FEAT / 128), dim3(32, 8)>>>(W);
    invn_kernel<<<43, 256>>>();
    gemm1_kernel<<<dim3(NT1, 16), 256, G1_SMEM>>>();   // launch idx 5 -> ncu target
    combine_kernel<<<2, 1024>>>();
    gemm2_kernel<<<dim3(8, 8), 256, G2_SMEM>>>();
    finalize_kernel<<<1, 1>>>(out);
}

// round 6
// speedup vs baseline: 1.2968x; 1.0626x over previous
#include <cuda_runtime.h>
#include <cuda_bf16.h>
#include <cuda_fp8.h>
#include <math.h>
#include <stdint.h>

#define BATCH 1024
#define FEAT  2048
#define NCLS  11003
#define NPAD  11008
#define NT1   172           // N tiles of 64 for gemm1
#define NCH   344           // 32-col LSE chunks (NPAD/32)
#define ROWS2 2048          // stacked [v; t]

#define ASCALE 64.0f
#define WSCALE 4.0f

// ---------------- device scratch (static, no runtime alloc) ----------------
__device__ __align__(128) __nv_bfloat16 g_abuf[ROWS2 * FEAT];   // normalized [v;t] bf16 (gemm2)
__device__ __align__(128) uint8_t g_a8[(size_t)ROWS2 * FEAT];   // fp8 v-hat * 64
__device__ __align__(128) uint8_t g_w8t[(size_t)NPAD * FEAT];   // fp8 W^T [n][k] * 4
__device__ float g_colsqp[16 * NPAD];   // per-128k col sq partials (fp32 W)
__device__ float g_invn[NPAD];          // 28 / (256 * ||W_col||)
__device__ float g_ll[ROWS2];           // label logits
__device__ float g_pmax[NCH * ROWS2];   // chunkwise lse partials
__device__ float g_psum[NCH * ROWS2];
__device__ float g_gal_part[256];
__device__ float g_inst_part[2];
__device__ int   g_lab[BATCH];

__device__ __forceinline__ uint8_t to_e4m3(float x) {
    __nv_fp8_e4m3 v(x);
    return *reinterpret_cast<uint8_t*>(&v);
}

// ---------------- prep: normalize rows + labels ----------------
__global__ void normalize_kernel(const float* __restrict__ vis,
                                 const float* __restrict__ txt,
                                 const int* __restrict__ lb) {
    int r = blockIdx.x;                 // 0..2047
    int t = threadIdx.x;                // 256 threads, 8 floats each

    if (r == 0) {
        // labels may be int32 (JAX canonicalization) or true int64; detect via
        // high words of the first 64 ints. lb[2i] read only after int64 confirmed.
        bool is64 = true;
        #pragma unroll
        for (int j = 1; j < 64; j += 2)
            if (lb[j] != 0) is64 = false;
        #pragma unroll
        for (int i = 0; i < 4; i++) {
            int idx = t + 256 * i;
            g_lab[idx] = is64 ? lb[2 * idx] : lb[idx];
        }
    }

    const float* src = (r < BATCH) ? (vis + (size_t)r * FEAT)
                                   : (txt + (size_t)(r - BATCH) * FEAT);
    float4 x0 = ((const float4*)src)[t];
    float4 x1 = ((const float4*)src)[t + 256];
    float ss = x0.x*x0.x + x0.y*x0.y + x0.z*x0.z + x0.w*x0.w
             + x1.x*x1.x + x1.y*x1.y + x1.z*x1.z + x1.w*x1.w;
    #pragma unroll
    for (int o = 16; o > 0; o >>= 1) ss += __shfl_xor_sync(0xffffffffu, ss, o);
    __shared__ float ws[8];
    __shared__ float s_rn;
    if ((t & 31) == 0) ws[t >> 5] = ss;
    __syncthreads();
    if (t == 0) {
        float s = 0.f;
        #pragma unroll
        for (int i = 0; i < 8; i++) s += ws[i];
        s_rn = rsqrtf(s);
    }
    __syncthreads();
    float rn = s_rn;
    __nv_bfloat162* dst = (__nv_bfloat162*)(g_abuf + (size_t)r * FEAT);
    dst[2*t]       = __nv_bfloat162(__float2bfloat16(x0.x*rn), __float2bfloat16(x0.y*rn));
    dst[2*t + 1]   = __nv_bfloat162(__float2bfloat16(x0.z*rn), __float2bfloat16(x0.w*rn));
    dst[512 + 2*t]     = __nv_bfloat162(__float2bfloat16(x1.x*rn), __float2bfloat16(x1.y*rn));
    dst[512 + 2*t + 1] = __nv_bfloat162(__float2bfloat16(x1.z*rn), __float2bfloat16(x1.w*rn));

    float fa = rn * ASCALE;
    uchar4 p0 = make_uchar4(to_e4m3(x0.x*fa), to_e4m3(x0.y*fa),
                            to_e4m3(x0.z*fa), to_e4m3(x0.w*fa));
    uchar4 p1 = make_uchar4(to_e4m3(x1.x*fa), to_e4m3(x1.y*fa),
                            to_e4m3(x1.z*fa), to_e4m3(x1.w*fa));
    uint32_t* d8 = (uint32_t*)(g_a8 + (size_t)r * FEAT);
    d8[t]       = *reinterpret_cast<uint32_t*>(&p0);
    d8[t + 256] = *reinterpret_cast<uint32_t*>(&p1);
}

// ---------------- prep: transpose W -> fp8 [n][k] + colsq partials ----------------
__global__ void wtrans_kernel(const float* __restrict__ W) {
    __shared__ float s[128][33];
    __shared__ float sq[8][33];
    int c0 = blockIdx.x * 32, k0 = blockIdx.y * 128;
    int tx = threadIdx.x, ty = threadIdx.y;
    int c = c0 + tx;
    float p = 0.f;
    #pragma unroll
    for (int i = 0; i < 16; i++) {
        int k = k0 + ty + 8 * i;
        float w = (c < NCLS) ? W[(size_t)k * NCLS + c] : 0.f;
        s[ty + 8 * i][tx] = w;
        p += w * w;
    }
    sq[ty][tx] = p;
    __syncthreads();
    if (ty == 0) {
        float ssum = 0.f;
        #pragma unroll
        for (int i = 0; i < 8; i++) ssum += sq[i][tx];
        g_colsqp[blockIdx.y * NPAD + c] = ssum;
    }
    #pragma unroll
    for (int j = 0; j < 4; j++) {
        int nl = ty + 8 * j;
        int kq = tx;
        uchar4 pk = make_uchar4(to_e4m3(s[4*kq+0][nl] * WSCALE),
                                to_e4m3(s[4*kq+1][nl] * WSCALE),
                                to_e4m3(s[4*kq+2][nl] * WSCALE),
                                to_e4m3(s[4*kq+3][nl] * WSCALE));
        *(uint32_t*)(g_w8t + (size_t)(c0 + nl) * FEAT + k0 + 4 * kq) =
            *reinterpret_cast<uint32_t*>(&pk);
    }
}

__global__ void invn_kernel() {
    int c = blockIdx.x * 256 + threadIdx.x;
    float s = 0.f;
    #pragma unroll
    for (int i = 0; i < 16; i++) s += g_colsqp[i * NPAD + c];
    g_invn[c] = (c < NCLS) ? (28.0f / (ASCALE * WSCALE)) * rsqrtf(s) : 0.f;
}

// ---------------- mma helpers ----------------
__device__ __forceinline__ void ldmx4(uint32_t* r, uint32_t a) {
    asm volatile("ldmatrix.sync.aligned.m8n8.x4.shared.b16 {%0,%1,%2,%3},[%4];\n"
                 : "=r"(r[0]), "=r"(r[1]), "=r"(r[2]), "=r"(r[3]) : "r"(a));
}
__device__ __forceinline__ void mma16816(float* c, const uint32_t* a, const uint32_t* b) {
    asm volatile("mma.sync.aligned.m16n8k16.row.col.f32.bf16.bf16.f32 "
                 "{%0,%1,%2,%3},{%4,%5,%6,%7},{%8,%9},{%0,%1,%2,%3};\n"
                 : "+f"(c[0]), "+f"(c[1]), "+f"(c[2]), "+f"(c[3])
                 : "r"(a[0]), "r"(a[1]), "r"(a[2]), "r"(a[3]),
                   "r"(b[0]), "r"(b[1]));
}
__device__ __forceinline__ void mma16832f8(float* c, const uint32_t* a, const uint32_t* b) {
    asm volatile("mma.sync.aligned.m16n8k32.row.col.f32.e4m3.e4m3.f32 "
                 "{%0,%1,%2,%3},{%4,%5,%6,%7},{%8,%9},{%0,%1,%2,%3};\n"
                 : "+f"(c[0]), "+f"(c[1]), "+f"(c[2]), "+f"(c[3])
                 : "r"(a[0]), "r"(a[1]), "r"(a[2]), "r"(a[3]),
                   "r"(b[0]), "r"(b[1]));
}
__device__ __forceinline__ void cpa16(uint32_t dst, const void* src) {
    asm volatile("cp.async.cg.shared.global [%0], [%1], 16;" :: "r"(dst), "l"(src));
}
__device__ __forceinline__ void cpa_commit() {
    asm volatile("cp.async.commit_group;" ::: "memory");
}
template <int N> __device__ __forceinline__ void cpa_wait() {
    asm volatile("cp.async.wait_group %0;" :: "n"(N) : "memory");
}

// ======================= GEMM1: fp8 128x64x128B, 3 CTAs/SM =======================
// 256 threads, 8 warps, warp tile 32x32: wm = warp&3, wn = warp>>2.
#define F8_ST   144
#define F8_AB   (128 * F8_ST)           // 18432
#define F8_BB   (64 * F8_ST)            // 9216
#define F8_STG  (F8_AB + F8_BB)         // 27648
#define G1_SMEM (2 * F8_STG)            // 55296
#define G1_NSTG 16                      // FEAT / 128

__global__ __launch_bounds__(256, 3) void gemm1_kernel() {
    extern __shared__ char smem[];
    __shared__ float sInv[64];
    int ntile = blockIdx.x, mtile = blockIdx.y;
    int tid = threadIdx.x, warp = tid >> 5, lane = tid & 31;
    int wm = warp & 3, wn = warp >> 2;
    if (tid < 64) sInv[tid] = g_invn[ntile * 64 + tid];

    uint32_t sb = (uint32_t)__cvta_generic_to_shared(smem);
    float c[2][4][4];
    #pragma unroll
    for (int mf = 0; mf < 2; mf++)
        #pragma unroll
        for (int nf = 0; nf < 4; nf++)
            #pragma unroll
            for (int j = 0; j < 4; j++) c[mf][nf][j] = 0.f;

    const uint8_t* Abase = g_a8 + (size_t)(mtile * 128) * FEAT;
    const uint8_t* Bbase = g_w8t + (size_t)(ntile * 64) * FEAT;

    auto issue_stage = [&](int kt, int buf) {
        uint32_t ab = sb + buf * F8_STG;
        uint32_t bb = ab + F8_AB;
        #pragma unroll
        for (int i = 0; i < 4; i++) {            // A: 128 rows x 128B
            int ch = tid + i * 256;
            int row = ch >> 3, q = ch & 7;
            cpa16(ab + row * F8_ST + q * 16,
                  Abase + (size_t)row * FEAT + kt * 128 + q * 16);
        }
        #pragma unroll
        for (int i = 0; i < 2; i++) {            // B: 64 rows x 128B
            int ch = tid + i * 256;
            int row = ch >> 3, q = ch & 7;
            cpa16(bb + row * F8_ST + q * 16,
                  Bbase + (size_t)row * FEAT + kt * 128 + q * 16);
        }
        cpa_commit();
    };

    issue_stage(0, 0);
    issue_stage(1, 1);

    for (int kt = 0; kt < G1_NSTG; kt++) {
        int buf = kt & 1;
        if (kt < G1_NSTG - 1) cpa_wait<1>(); else cpa_wait<0>();
        __syncthreads();

        uint32_t ab = sb + buf * F8_STG;
        uint32_t bb = ab + F8_AB;
        #pragma unroll
        for (int ks = 0; ks < 4; ks++) {         // 4 x k32
            uint32_t a[2][4], b[4][2];
            #pragma unroll
            for (int mf = 0; mf < 2; mf++)
                ldmx4(a[mf], ab + (wm * 32 + mf * 16 + (lane & 15)) * F8_ST +
                              ks * 32 + ((lane >> 4) << 4));
            #pragma unroll
            for (int nh = 0; nh < 2; nh++) {
                uint32_t r[4];
                int nrow = wn * 32 + nh * 16 + (lane & 7) + ((lane >> 4) << 3);
                int kcol = ks * 32 + (((lane >> 3) & 1) << 4);
                ldmx4(r, bb + nrow * F8_ST + kcol);
                b[nh * 2][0] = r[0]; b[nh * 2][1] = r[1];
                b[nh * 2 + 1][0] = r[2]; b[nh * 2 + 1][1] = r[3];
            }
            #pragma unroll
            for (int mf = 0; mf < 2; mf++)
                #pragma unroll
                for (int nf = 0; nf < 4; nf++)
                    mma16832f8(c[mf][nf], a[mf], b[nf]);
        }
        __syncthreads();
        if (kt + 2 < G1_NSTG) issue_stage(kt + 2, buf);
    }

    // -------- epilogue: chunkwise logsumexp (32-col chunks) --------
    int g = lane >> 2, tg = lane & 3;
    #pragma unroll
    for (int mf = 0; mf < 2; mf++)
        #pragma unroll
        for (int pr = 0; pr < 2; pr++) {
            int R = mtile * 128 + wm * 32 + mf * 16 + pr * 8 + g;
            int lbl = g_lab[R & (BATCH - 1)];
            float v[8];
            float mx = -1e30f;
            #pragma unroll
            for (int nf = 0; nf < 4; nf++)
                #pragma unroll
                for (int j = 0; j < 2; j++) {
                    int nl = wn * 32 + nf * 8 + tg * 2 + j;
                    int n = ntile * 64 + nl;
                    float val = c[mf][nf][pr * 2 + j] * sInv[nl];
                    if (n >= NCLS) val = -1e30f;
                    if (n == lbl) g_ll[R] = val;
                    v[nf * 2 + j] = val;
                    mx = fmaxf(mx, val);
                }
            mx = fmaxf(mx, __shfl_xor_sync(0xffffffffu, mx, 1));
            mx = fmaxf(mx, __shfl_xor_sync(0xffffffffu, mx, 2));
            float s = 0.f;
            #pragma unroll
            for (int i = 0; i < 8; i++) s += __expf(v[i] - mx);
            s += __shfl_xor_sync(0xffffffffu, s, 1);
            s += __shfl_xor_sync(0xffffffffu, s, 2);
            if (tg == 0) {
                int chunk = ntile * 2 + wn;
                g_pmax[chunk * ROWS2 + R] = mx;
                g_psum[chunk * ROWS2 + R] = s;
            }
        }
}

// ======================= GEMM2: bf16 64x64x64, high-utilization =======================
// 128 threads, 4 warps, warp tile 32x32: wm = warp&1, wn = warp>>1. 3-stage.
#define B2_ST   72
#define B2_TB   (64 * B2_ST * 2)        // 9216
#define G2_STG  (2 * B2_TB)             // 18432
#define G2_SMEM (3 * G2_STG)            // 55296
#define NSTG2   32

__global__ __launch_bounds__(128, 4) void gemm2_kernel() {
    extern __shared__ char smem[];
    int ntile = blockIdx.x, mtile = blockIdx.y;
    int tid = threadIdx.x, warp = tid >> 5, lane = tid & 31;
    int wm = warp & 1, wn = warp >> 1;
    uint32_t sb = (uint32_t)__cvta_generic_to_shared(smem);

    float c[2][4][4];
    #pragma unroll
    for (int mf = 0; mf < 2; mf++)
        #pragma unroll
        for (int nf = 0; nf < 4; nf++)
            #pragma unroll
            for (int j = 0; j < 4; j++) c[mf][nf][j] = 0.f;

    const __nv_bfloat16* Abase = g_abuf + (size_t)(mtile * 64) * FEAT;
    const __nv_bfloat16* Bbase = g_abuf + (size_t)(BATCH + ntile * 64) * FEAT;

    auto issue_stage = [&](int kt, int buf) {
        uint32_t ab = sb + buf * G2_STG;
        uint32_t bb = ab + B2_TB;
        #pragma unroll
        for (int i = 0; i < 4; i++) {            // A: 64 rows x 64 bf16
            int ch = tid + i * 128;
            int row = ch >> 3, q = ch & 7;
            cpa16(ab + row * 144 + q * 16,
                  Abase + (size_t)row * FEAT + kt * 64 + q * 8);
        }
        #pragma unroll
        for (int i = 0; i < 4; i++) {            // B: 64 rows x 64 bf16
            int ch = tid + i * 128;
            int row = ch >> 3, q = ch & 7;
            cpa16(bb + row * 144 + q * 16,
                  Bbase + (size_t)row * FEAT + kt * 64 + q * 8);
        }
        cpa_commit();
    };

    issue_stage(0, 0);
    issue_stage(1, 1);

    for (int kt = 0; kt < NSTG2; kt++) {
        int buf = kt % 3;
        if (kt < NSTG2 - 1) cpa_wait<1>(); else cpa_wait<0>();
        __syncthreads();
        if (kt + 2 < NSTG2) issue_stage(kt + 2, (kt + 2) % 3);

        uint32_t ab = sb + buf * G2_STG;
        uint32_t bb = ab + B2_TB;
        #pragma unroll
        for (int ks = 0; ks < 4; ks++) {
            uint32_t a[2][4], b[4][2];
            #pragma unroll
            for (int mf = 0; mf < 2; mf++)
                ldmx4(a[mf], ab + ((wm * 32 + mf * 16 + (lane & 15)) * B2_ST +
                                   ks * 16 + ((lane >> 4) << 3)) * 2);
            #pragma unroll
            for (int nh = 0; nh < 2; nh++) {
                uint32_t r[4];
                int nrow = wn * 32 + nh * 16 + (lane & 7) + ((lane >> 4) << 3);
                int kcol = ks * 16 + (((lane >> 3) & 1) << 3);
                ldmx4(r, bb + (nrow * B2_ST + kcol) * 2);
                b[nh * 2][0] = r[0]; b[nh * 2][1] = r[1];
                b[nh * 2 + 1][0] = r[2]; b[nh * 2 + 1][1] = r[3];
            }
            #pragma unroll
            for (int mf = 0; mf < 2; mf++)
                #pragma unroll
                for (int nf = 0; nf < 4; nf++)
                    mma16816(c[mf][nf], a[mf], b[nf]);
        }
        __syncthreads();
    }

    int g = lane >> 2, tg = lane & 3;
    float local = 0.f;
    #pragma unroll
    for (int mf = 0; mf < 2; mf++)
        #pragma unroll
        for (int pr = 0; pr < 2; pr++) {
            int R = mtile * 64 + wm * 32 + mf * 16 + pr * 8 + g;
            int lr = g_lab[R];
            #pragma unroll
            for (int nf = 0; nf < 4; nf++)
                #pragma unroll
                for (int j = 0; j < 2; j++) {
                    int n = ntile * 64 + wn * 32 + nf * 8 + tg * 2 + j;
                    int lc = g_lab[n];
                    float s = c[mf][nf][pr * 2 + j];
                    float x = (lr == lc) ? (-10.f * (s - 0.6f))
                                         : (40.f * (s - 0.4f));
                    local += (x > 15.f) ? x : log1pf(__expf(x));
                }
        }
    #pragma unroll
    for (int o = 16; o > 0; o >>= 1) local += __shfl_xor_sync(0xffffffffu, local, o);
    __shared__ float ws[4];
    if (lane == 0) ws[warp] = local;
    __syncthreads();
    if (tid == 0)
        g_gal_part[blockIdx.y * gridDim.x + blockIdx.x] = ws[0] + ws[1] + ws[2] + ws[3];
}

// ---------------- combine: per-row lse + CE partial ----------------
__global__ void combine_kernel() {
    int r = blockIdx.x * 1024 + threadIdx.x;     // 2 blocks x 1024
    float mx = -1e30f;
    for (int i = 0; i < NCH; i++) mx = fmaxf(mx, g_pmax[i * ROWS2 + r]);
    float s = 0.f;
    for (int i = 0; i < NCH; i++)
        s += g_psum[i * ROWS2 + r] * __expf(g_pmax[i * ROWS2 + r] - mx);
    float contrib = mx + logf(s) - g_ll[r];

    int lane = threadIdx.x & 31, wid = threadIdx.x >> 5;
    #pragma unroll
    for (int o = 16; o > 0; o >>= 1) contrib += __shfl_xor_sync(0xffffffffu, contrib, o);
    __shared__ float ws[32];
    if (lane == 0) ws[wid] = contrib;
    __syncthreads();
    if (threadIdx.x < 32) {
        float v = ws[threadIdx.x];
        #pragma unroll
        for (int o = 16; o > 0; o >>= 1) v += __shfl_xor_sync(0xffffffffu, v, o);
        if (threadIdx.x == 0) g_inst_part[blockIdx.x] = v;
    }
}

__global__ void finalize_kernel(float* __restrict__ out) {
    float inst = (g_inst_part[0] + g_inst_part[1]) * (1.0f / BATCH);
    float gal = 0.f;
    for (int i = 0; i < 256; i++) gal += g_gal_part[i];
    out[0] = inst;
    out[1] = 2.0f * gal / BATCH;
}

// ---------------- launch ----------------
extern "C" void kernel_launch(void* const* d_in, const int* in_sizes, int n_in,
                              void* d_out, int out_size) {
    const float* vis = (const float*)d_in[0];
    const float* txt = (const float*)d_in[1];
    const int* lab = (const int*)d_in[2];
    const float* W = (const float*)d_in[3];
    float* out = (float*)d_out;

    cudaFuncSetAttribute(gemm1_kernel,
                         cudaFuncAttributeMaxDynamicSharedMemorySize, G1_SMEM);
    cudaFuncSetAttribute(gemm2_kernel,
                         cudaFuncAttributeMaxDynamicSharedMemorySize, G2_SMEM);

    normalize_kernel<<<ROWS2, 256>>>(vis, txt, lab);
    wtrans_kernel<<<dim3(NPAD / 32, FEAT / 128), dim3(32, 8)>>>(W);
    invn_kernel<<<43, 256>>>();
    gemm1_kernel<<<dim3(NT1, 16), 256, G1_SMEM>>>();   // ncu target (launch idx 5)
    combine_kernel<<<2, 1024>>>();
    gemm2_kernel<<<dim3(16, 16), 128, G2_SMEM>>>();
    finalize_kernel<<<1, 1>>>(out);
}